// round 4
// baseline (speedup 1.0000x reference)
#include <cuda_runtime.h>
#include <cuda_bf16.h>
#include <cstdint>

// Shapes fixed by setup_inputs: L=4, B=8, C=256, H=64, W=64
#define L_DIM 4
#define B_DIM 8
#define C_DIM 256
#define SPATIAL 4096
#define S4 (SPATIAL / 4)                 // 1024 float4 per slab
#define SLABS_PER_B (L_DIM * C_DIM)      // 1024 slabs per batch
#define BPG 74                           // blocks per batch-group
#define GRID_X (B_DIM * BPG)             // 592 = 148 SMs * 4 blocks
#define INV_SPATIAL (1.0f / 4096.0f)

// Cross-block state (allocation-free rule -> __device__ globals, zero-init).
__device__ float    g_gap[B_DIM][L_DIM * C_DIM];
__device__ unsigned g_gap_done[B_DIM];
__device__ unsigned g_exit_count;

__global__ __launch_bounds__(256) void sffm_fused(const float* __restrict__ in,
                                                  const float* __restrict__ Wm,
                                                  float* __restrict__ out) {
    const int bid  = blockIdx.x;
    const int b    = bid / BPG;          // batch group
    const int j    = bid - b * BPG;      // block index within group
    const int t    = threadIdx.x;
    const int lane = t & 31;
    const int warp = t >> 5;

    __shared__ float gap_sm[L_DIM * C_DIM];  // 4 KB staged gap for this batch
    __shared__ float a_sm[16];               // attn scalar per owned slab
    __shared__ float ws[2][8];               // cross-warp reduce scratch

    // ---- stagger: start only after previous group's GAP completed ----
    // (forward-only wait: group g waits only on lower-bid blocks -> no deadlock)
    if (b > 0 && t == 0) {
        while (*(volatile unsigned*)&g_gap_done[b - 1] < BPG) __nanosleep(128);
    }
    __syncthreads();

    // owned slabs: local index s = j + k*BPG (< 1024); l = s>>8, c = s&255
    int nslab = 0;
    for (int s = j; s < SLABS_PER_B; s += BPG) nslab++;   // 13 or 14

    const float4* in4 = (const float4*)in;

    // ================= Phase 1: GAP (pairwise slabs for MLP=8) =================
    for (int k0 = 0; k0 < nslab; k0 += 2) {
        int  s0   = j + k0 * BPG;
        int  s1   = s0 + BPG;
        bool has1 = (k0 + 1) < nslab;
        int  l0 = s0 >> 8, c0 = s0 & 255;
        size_t base0 = ((size_t)((l0 * B_DIM + b) * C_DIM + c0)) * S4;
        float4 v0[4], v1[4];
#pragma unroll
        for (int i = 0; i < 4; i++) v0[i] = in4[base0 + t + i * 256];
        int l1 = 0, c1 = 0;
        if (has1) {
            l1 = s1 >> 8; c1 = s1 & 255;
            size_t base1 = ((size_t)((l1 * B_DIM + b) * C_DIM + c1)) * S4;
#pragma unroll
            for (int i = 0; i < 4; i++) v1[i] = in4[base1 + t + i * 256];
        }
        float r0 = 0.f, r1 = 0.f;
#pragma unroll
        for (int i = 0; i < 4; i++) r0 += (v0[i].x + v0[i].y) + (v0[i].z + v0[i].w);
        if (has1) {
#pragma unroll
            for (int i = 0; i < 4; i++) r1 += (v1[i].x + v1[i].y) + (v1[i].z + v1[i].w);
        }
#pragma unroll
        for (int o = 16; o; o >>= 1) {
            r0 += __shfl_xor_sync(0xffffffffu, r0, o);
            r1 += __shfl_xor_sync(0xffffffffu, r1, o);
        }
        if (lane == 0) { ws[0][warp] = r0; ws[1][warp] = r1; }
        __syncthreads();
        if (t == 0) {
            float a0 = 0.f, a1 = 0.f;
#pragma unroll
            for (int w = 0; w < 8; w++) { a0 += ws[0][w]; a1 += ws[1][w]; }
            g_gap[b][l0 * C_DIM + c0] = a0 * INV_SPATIAL;
            if (has1) g_gap[b][l1 * C_DIM + c1] = a1 * INV_SPATIAL;
        }
        __syncthreads();
    }
    if (t == 0) { __threadfence(); atomicAdd(&g_gap_done[b], 1u); }

    // ---- group barrier: all 74 blocks of this batch finished GAP ----
    if (t == 0) {
        while (*(volatile unsigned*)&g_gap_done[b] < BPG) __nanosleep(128);
        __threadfence();
    }
    __syncthreads();

    // stage this batch's gap into smem (1 KB x4, L2-hot)
    for (int i = t; i < L_DIM * C_DIM; i += 256) gap_sm[i] = g_gap[b][i];
    __syncthreads();

    // ========== Phase 2: attn scalars for the channels this block owns =========
    // score[l] = sum_c gap[l][c] * W[q][c]  (row q of W, coalesced float4 reads)
    for (int k = warp; k < nslab; k += 8) {
        int s = j + k * BPG;
        int lsel = s >> 8, q = s & 255;
        const float4* wr = (const float4*)(Wm + (size_t)q * C_DIM);
        const float4* g4 = (const float4*)gap_sm;
        float s0 = 0.f, s1 = 0.f, s2 = 0.f, s3 = 0.f;
#pragma unroll
        for (int ii = 0; ii < 2; ii++) {
            int i = lane + ii * 32;
            float4 wv = wr[i];
            float4 a0 = g4[0 * 64 + i];
            float4 a1 = g4[1 * 64 + i];
            float4 a2 = g4[2 * 64 + i];
            float4 a3 = g4[3 * 64 + i];
            s0 += wv.x * a0.x + wv.y * a0.y + wv.z * a0.z + wv.w * a0.w;
            s1 += wv.x * a1.x + wv.y * a1.y + wv.z * a1.z + wv.w * a1.w;
            s2 += wv.x * a2.x + wv.y * a2.y + wv.z * a2.z + wv.w * a2.w;
            s3 += wv.x * a3.x + wv.y * a3.y + wv.z * a3.z + wv.w * a3.w;
        }
#pragma unroll
        for (int o = 16; o; o >>= 1) {
            s0 += __shfl_xor_sync(0xffffffffu, s0, o);
            s1 += __shfl_xor_sync(0xffffffffu, s1, o);
            s2 += __shfl_xor_sync(0xffffffffu, s2, o);
            s3 += __shfl_xor_sync(0xffffffffu, s3, o);
        }
        if (lane == 0) {
            float m  = fmaxf(fmaxf(s0, s1), fmaxf(s2, s3));
            float e0 = __expf(s0 - m), e1 = __expf(s1 - m);
            float e2 = __expf(s2 - m), e3 = __expf(s3 - m);
            float inv = 1.0f / (e0 + e1 + e2 + e3);
            float sel = (lsel == 0) ? e0 : (lsel == 1) ? e1 : (lsel == 2) ? e2 : e3;
            a_sm[k] = sel * inv;
        }
    }
    __syncthreads();

    // ============ Phase 3: scale own slabs (re-read is L2/L1-hot) ==============
    float4* out4 = (float4*)out;
    for (int k = 0; k < nslab; k++) {
        int s = j + k * BPG;
        int l = s >> 8, c = s & 255;
        float a = a_sm[k];
        size_t base = ((size_t)((l * B_DIM + b) * C_DIM + c)) * S4;
#pragma unroll
        for (int i = 0; i < 4; i++) {
            float4 v = in4[base + t + i * 256];
            v.x *= a; v.y *= a; v.z *= a; v.w *= a;
            out4[base + t + i * 256] = v;
        }
    }

    // ---- reset cross-launch state (last block out resets; replay-safe) ----
    __syncthreads();
    if (t == 0) {
        __threadfence();
        unsigned v = atomicAdd(&g_exit_count, 1u);
        if (v == GRID_X - 1) {
#pragma unroll
            for (int i = 0; i < B_DIM; i++) g_gap_done[i] = 0;
            __threadfence();
            g_exit_count = 0;
        }
    }
}

extern "C" void kernel_launch(void* const* d_in, const int* in_sizes, int n_in,
                              void* d_out, int out_size) {
    const float* in  = (const float*)d_in[0];   // [L,B,C,H,W]
    const float* Wm  = (const float*)d_in[1];   // [C,C]
    float*       out = (float*)d_out;           // [L,B,C,H,W]

    sffm_fused<<<GRID_X, 256>>>(in, Wm, out);
}

// round 6
// speedup vs baseline: 1.6700x; 1.6700x over previous
#include <cuda_runtime.h>
#include <cuda_bf16.h>
#include <cstdint>

// Shapes fixed by setup_inputs: L=4, B=8, C=256, H=64, W=64
#define L_DIM 4
#define B_DIM 8
#define C_DIM 256
#define SPATIAL 4096
#define S4 (SPATIAL / 4)                 // 1024 float4 per slab
#define SLABS_PER_B (L_DIM * C_DIM)      // 1024 slabs per batch
#define BPG 74                           // blocks per batch-group
#define GRID_X (B_DIM * BPG)             // 592 = 148 SMs * 4 blocks
#define INV_SPATIAL (1.0f / 4096.0f)

// Cross-block state (allocation-free rule -> __device__ globals, zero-init).
__device__ float    g_gap[B_DIM][L_DIM * C_DIM];
__device__ unsigned g_gap_done[B_DIM];
__device__ unsigned g_exit_count;

__global__ __launch_bounds__(256) void sffm_fused(const float* __restrict__ in,
                                                  const float* __restrict__ Wm,
                                                  float* __restrict__ out) {
    const int bid  = blockIdx.x;
    const int b    = bid / BPG;          // batch group — ALL groups run concurrently
    const int j    = bid - b * BPG;      // block index within group
    const int t    = threadIdx.x;
    const int lane = t & 31;
    const int warp = t >> 5;

    __shared__ float gap_sm[L_DIM * C_DIM];  // 4 KB staged gap for this batch
    __shared__ float a_sm[16];               // attn scalar per owned slab
    __shared__ float ws[2][8];               // cross-warp reduce scratch

    // owned slabs: s = j + k*BPG (< 1024); l = s>>8, c = s&255
    int nslab = 0;
    for (int s = j; s < SLABS_PER_B; s += BPG) nslab++;   // 13 or 14

    const float4* in4 = (const float4*)in;

    // ================= Phase 1: GAP (pairwise slabs for MLP=8) =================
    for (int k0 = 0; k0 < nslab; k0 += 2) {
        int  s0   = j + k0 * BPG;
        int  s1   = s0 + BPG;
        bool has1 = (k0 + 1) < nslab;
        int  l0 = s0 >> 8, c0 = s0 & 255;
        size_t base0 = ((size_t)((l0 * B_DIM + b) * C_DIM + c0)) * S4;
        float4 v0[4], v1[4];
#pragma unroll
        for (int i = 0; i < 4; i++) v0[i] = in4[base0 + t + i * 256];
        int l1 = 0, c1 = 0;
        if (has1) {
            l1 = s1 >> 8; c1 = s1 & 255;
            size_t base1 = ((size_t)((l1 * B_DIM + b) * C_DIM + c1)) * S4;
#pragma unroll
            for (int i = 0; i < 4; i++) v1[i] = in4[base1 + t + i * 256];
        }
        float r0 = 0.f, r1 = 0.f;
#pragma unroll
        for (int i = 0; i < 4; i++) r0 += (v0[i].x + v0[i].y) + (v0[i].z + v0[i].w);
        if (has1) {
#pragma unroll
            for (int i = 0; i < 4; i++) r1 += (v1[i].x + v1[i].y) + (v1[i].z + v1[i].w);
        }
#pragma unroll
        for (int o = 16; o; o >>= 1) {
            r0 += __shfl_xor_sync(0xffffffffu, r0, o);
            r1 += __shfl_xor_sync(0xffffffffu, r1, o);
        }
        if (lane == 0) { ws[0][warp] = r0; ws[1][warp] = r1; }
        __syncthreads();
        if (t == 0) {
            float a0 = 0.f, a1 = 0.f;
#pragma unroll
            for (int w = 0; w < 8; w++) { a0 += ws[0][w]; a1 += ws[1][w]; }
            g_gap[b][l0 * C_DIM + c0] = a0 * INV_SPATIAL;
            if (has1) g_gap[b][l1 * C_DIM + c1] = a1 * INV_SPATIAL;
        }
        __syncthreads();
    }
    if (t == 0) { __threadfence(); atomicAdd(&g_gap_done[b], 1u); }

    // ---- group barrier: only waits on this batch's own 74 blocks ----
    if (t == 0) {
        while (*(volatile unsigned*)&g_gap_done[b] < BPG) __nanosleep(64);
        __threadfence();
    }
    __syncthreads();

    // stage this batch's gap into smem (4 KB, L2-hot)
    for (int i = t; i < L_DIM * C_DIM; i += 256) gap_sm[i] = g_gap[b][i];
    __syncthreads();

    // ========== Phase 2: attn scalars for the slabs this block owns ===========
    // score[l] = sum_c gap[l][c] * W[q][c]  (coalesced per-warp float4 row dot)
    for (int k = warp; k < nslab; k += 8) {
        int s = j + k * BPG;
        int lsel = s >> 8, q = s & 255;
        const float4* wr = (const float4*)(Wm + (size_t)q * C_DIM);
        const float4* g4 = (const float4*)gap_sm;
        float s0 = 0.f, s1 = 0.f, s2 = 0.f, s3 = 0.f;
#pragma unroll
        for (int ii = 0; ii < 2; ii++) {
            int i = lane + ii * 32;
            float4 wv = wr[i];
            float4 a0 = g4[0 * 64 + i];
            float4 a1 = g4[1 * 64 + i];
            float4 a2 = g4[2 * 64 + i];
            float4 a3 = g4[3 * 64 + i];
            s0 += wv.x * a0.x + wv.y * a0.y + wv.z * a0.z + wv.w * a0.w;
            s1 += wv.x * a1.x + wv.y * a1.y + wv.z * a1.z + wv.w * a1.w;
            s2 += wv.x * a2.x + wv.y * a2.y + wv.z * a2.z + wv.w * a2.w;
            s3 += wv.x * a3.x + wv.y * a3.y + wv.z * a3.z + wv.w * a3.w;
        }
#pragma unroll
        for (int o = 16; o; o >>= 1) {
            s0 += __shfl_xor_sync(0xffffffffu, s0, o);
            s1 += __shfl_xor_sync(0xffffffffu, s1, o);
            s2 += __shfl_xor_sync(0xffffffffu, s2, o);
            s3 += __shfl_xor_sync(0xffffffffu, s3, o);
        }
        if (lane == 0) {
            float m  = fmaxf(fmaxf(s0, s1), fmaxf(s2, s3));
            float e0 = __expf(s0 - m), e1 = __expf(s1 - m);
            float e2 = __expf(s2 - m), e3 = __expf(s3 - m);
            float inv = 1.0f / (e0 + e1 + e2 + e3);
            float sel = (lsel == 0) ? e0 : (lsel == 1) ? e1 : (lsel == 2) ? e2 : e3;
            a_sm[k] = sel * inv;
        }
    }
    __syncthreads();

    // ============ Phase 3: scale own slabs, DESCENDING (MRU-first) =============
    // Re-read walks the L2-resident data newest-first to avoid the LRU
    // eviction cascade; __ldcs (last use) + __stcs (don't pollute L2).
    float4* out4 = (float4*)out;
    for (int k = nslab - 1; k >= 0; k--) {
        int s = j + k * BPG;
        int l = s >> 8, c = s & 255;
        float a = a_sm[k];
        size_t base = ((size_t)((l * B_DIM + b) * C_DIM + c)) * S4;
        float4 v[4];
#pragma unroll
        for (int i = 3; i >= 0; i--) v[i] = __ldcs(in4 + base + t + i * 256);
#pragma unroll
        for (int i = 3; i >= 0; i--) {
            float4 w = v[i];
            w.x *= a; w.y *= a; w.z *= a; w.w *= a;
            __stcs(out4 + base + t + i * 256, w);
        }
    }

    // ---- reset cross-launch state (last block out resets; replay-safe) ----
    __syncthreads();
    if (t == 0) {
        __threadfence();
        unsigned v = atomicAdd(&g_exit_count, 1u);
        if (v == GRID_X - 1) {
#pragma unroll
            for (int i = 0; i < B_DIM; i++) g_gap_done[i] = 0;
            __threadfence();
            g_exit_count = 0;
        }
    }
}

extern "C" void kernel_launch(void* const* d_in, const int* in_sizes, int n_in,
                              void* d_out, int out_size) {
    const float* in  = (const float*)d_in[0];   // [L,B,C,H,W]
    const float* Wm  = (const float*)d_in[1];   // [C,C]
    float*       out = (float*)d_out;           // [L,B,C,H,W]

    sffm_fused<<<GRID_X, 256>>>(in, Wm, out);
}